// round 1
// baseline (speedup 1.0000x reference)
#include <cuda_runtime.h>
#include <stdint.h>

// ---------------------------------------------------------------------------
// AdaptiveUnpooling:
//   out[perm[i]] = x_abstract[i]
//   for missing node t (not in perm): out[t] = mean over unique non-self
//   neighbors s of x0[s]  (x0[s]=0 if s missing), if it has >=1 unique
//   neighbor; else 0.
//
// Strategy:
//   - pos[n] = pooled row index of node n, or -1 (missing).
//   - dedup directed pairs (t,s) with missing t via a 64-bit open-addressing
//     hash table (atomicCAS). Winner increments cnt[t]; if source is present,
//     appends (t, pos[s]) to a worklist.
//   - warp-per-worklist-item accumulates x_abstract[pos[s]] into out[t] with
//     float atomics.
//   - finalize divides missing rows by cnt.
// ---------------------------------------------------------------------------

#define TAB_BITS 23
#define TAB_SIZE (1u << TAB_BITS)      // 8.4M slots * 8B = 64MB
#define MAX_N    131072                // >= 100000
#define WL_MAX   2600000               // >= 2*E upper bound

__device__ unsigned long long g_hash[TAB_SIZE];
__device__ int  g_cnt[MAX_N];
__device__ int  g_pos[MAX_N];
__device__ int  g_wl_count;
__device__ int2 g_wl[WL_MAX];

__device__ __forceinline__ uint64_t mix64(uint64_t x) {
    x ^= x >> 33; x *= 0xff51afd7ed558ccdULL;
    x ^= x >> 33; x *= 0xc4ceb9fe1a85ec53ULL;
    x ^= x >> 33;
    return x;
}

// Zero hash table, output, counters; pos = -1; worklist count = 0.
__global__ void clear_kernel(float4* out4, int total_out4, int N) {
    const int stride = gridDim.x * blockDim.x;
    const int tid = blockIdx.x * blockDim.x + threadIdx.x;
    for (unsigned i = tid; i < TAB_SIZE; i += stride) g_hash[i] = 0ULL;
    for (int i = tid; i < total_out4; i += stride)
        out4[i] = make_float4(0.f, 0.f, 0.f, 0.f);
    for (int i = tid; i < N; i += stride) { g_cnt[i] = 0; g_pos[i] = -1; }
    if (tid == 0) g_wl_count = 0;
}

// pos[perm[i]] = i; out[perm[i]] = x_abstract[i]
__global__ void scatter_kernel(const float4* __restrict__ x4,
                               const int* __restrict__ perm,
                               float4* __restrict__ out4,
                               int P, int Cv) {
    const int stride = gridDim.x * blockDim.x;
    const int tid = blockIdx.x * blockDim.x + threadIdx.x;
    for (int i = tid; i < P; i += stride) g_pos[perm[i]] = i;
    const int total = P * Cv;
    for (int i = tid; i < total; i += stride) {
        int r = i / Cv;
        int c = i - r * Cv;
        out4[(size_t)perm[r] * Cv + c] = x4[i];
    }
}

// One thread per directed pair. Dedup via hash; count + worklist on first win.
__global__ void edge_kernel(const int* __restrict__ e0,
                            const int* __restrict__ e1,
                            int E, int N) {
    const int j = blockIdx.x * blockDim.x + threadIdx.x;
    if (j >= 2 * E) return;
    int t, s;
    if (j < E) { t = e0[j];     s = e1[j];     }
    else       { t = e1[j - E]; s = e0[j - E]; }
    if (t == s) return;                 // drop self-loops
    if (g_pos[t] >= 0) return;          // only missing targets need neighbors

    const uint64_t key = (uint64_t)t * (uint64_t)N + (uint64_t)s + 1ULL;
    unsigned h = (unsigned)(mix64(key)) & (TAB_SIZE - 1);
    while (true) {
        unsigned long long old = atomicCAS(&g_hash[h], 0ULL, key);
        if (old == 0ULL) {              // first occurrence of this (t,s)
            atomicAdd(&g_cnt[t], 1);
            int ps = g_pos[s];
            if (ps >= 0) {              // only present sources carry features
                int w = atomicAdd(&g_wl_count, 1);
                g_wl[w] = make_int2(t, ps);
            }
            return;
        }
        if (old == key) return;         // duplicate
        h = (h + 1) & (TAB_SIZE - 1);
    }
}

// Warp per worklist item: out[t] += x_abstract[ps]  (64 float atomics/item)
__global__ void feat_kernel(const float* __restrict__ xa,
                            float* __restrict__ out, int C) {
    const int lane   = threadIdx.x & 31;
    const int warp   = (blockIdx.x * blockDim.x + threadIdx.x) >> 5;
    const int nwarps = (gridDim.x * blockDim.x) >> 5;
    const int n = g_wl_count;
    for (int i = warp; i < n; i += nwarps) {
        int2 w = g_wl[i];
        const float* src = xa  + (size_t)w.y * C;
        float*       dst = out + (size_t)w.x * C;
        #pragma unroll 2
        for (int c = lane; c < C; c += 32)
            atomicAdd(&dst[c], src[c]);
    }
}

// Divide missing rows by their unique-neighbor count.
__global__ void finalize_kernel(float4* __restrict__ out4, int N, int Cv) {
    const int stride = gridDim.x * blockDim.x;
    const int tid = blockIdx.x * blockDim.x + threadIdx.x;
    const int total = N * Cv;
    for (int i = tid; i < total; i += stride) {
        int n = i / Cv;
        if (g_pos[n] < 0) {
            int c = g_cnt[n];
            if (c > 0) {
                float inv = 1.0f / (float)c;
                float4 v = out4[i];
                v.x *= inv; v.y *= inv; v.z *= inv; v.w *= inv;
                out4[i] = v;
            }
        }
    }
}

extern "C" void kernel_launch(void* const* d_in, const int* in_sizes, int n_in,
                              void* d_out, int out_size) {
    const float* xa   = (const float*)d_in[0];   // [P, C] f32
    const int*   perm = (const int*)d_in[1];     // [P]
    const int*   ei   = (const int*)d_in[2];     // [2, E]
    (void)n_in;

    const int P  = in_sizes[1];
    const int C  = in_sizes[0] / P;              // 64
    const int Cv = C / 4;
    const int E  = in_sizes[2] / 2;
    const int N  = out_size / C;                 // 100000
    float* out = (float*)d_out;

    clear_kernel<<<2048, 256>>>((float4*)out, out_size / 4, N);

    {
        int work = P * Cv;
        int blocks = (work + 255) / 256;
        if (blocks > 4096) blocks = 4096;
        scatter_kernel<<<blocks, 256>>>((const float4*)xa, perm, (float4*)out, P, Cv);
    }

    {
        int blocks = (2 * E + 255) / 256;
        edge_kernel<<<blocks, 256>>>(ei, ei + E, E, N);
    }

    feat_kernel<<<2048, 256>>>(xa, out, C);

    finalize_kernel<<<2048, 256>>>((float4*)out, N, Cv);
}

// round 2
// speedup vs baseline: 1.7762x; 1.7762x over previous
#include <cuda_runtime.h>
#include <stdint.h>

// ---------------------------------------------------------------------------
// AdaptiveUnpooling:
//   out[perm[i]] = x_abstract[i]
//   missing node t: out[t] = mean over unique non-self neighbors s of x0[s]
//   (x0[s]=0 if s missing), if >=1 unique neighbor; else 0.
//
// v2: warp-aggregated worklist append (kills single-counter serialization),
//     both edge directions per thread, 32MB hash, no full-output clear,
//     red.global.add.v4.f32 feature accumulation.
// ---------------------------------------------------------------------------

#define TAB_BITS 22
#define TAB_SIZE (1u << TAB_BITS)      // 4M slots * 8B = 32MB (L2-resident)
#define MAX_N    131072
#define WL_MAX   2600000

__device__ unsigned long long g_hash[TAB_SIZE];
__device__ int  g_cnt[MAX_N];
__device__ int  g_pos[MAX_N];
__device__ int  g_wl_count;
__device__ int2 g_wl[WL_MAX];

__device__ __forceinline__ uint64_t mix64(uint64_t x) {
    x ^= x >> 33; x *= 0xff51afd7ed558ccdULL;
    x ^= x >> 33; x *= 0xc4ceb9fe1a85ec53ULL;
    x ^= x >> 33;
    return x;
}

// Zero hash table + counters; pos = -1; worklist count = 0. (No output clear.)
__global__ void clear_kernel(int N) {
    const int stride = gridDim.x * blockDim.x;
    const int tid = blockIdx.x * blockDim.x + threadIdx.x;
    ulonglong2* h2 = reinterpret_cast<ulonglong2*>(g_hash);
    for (unsigned i = tid; i < TAB_SIZE / 2; i += stride)
        h2[i] = make_ulonglong2(0ULL, 0ULL);
    for (int i = tid; i < N; i += stride) { g_cnt[i] = 0; g_pos[i] = -1; }
    if (tid == 0) g_wl_count = 0;
}

// pos[perm[i]] = i
__global__ void pos_kernel(const int* __restrict__ perm, int P) {
    const int i = blockIdx.x * blockDim.x + threadIdx.x;
    if (i < P) g_pos[perm[i]] = i;
}

// Present rows: copy from x_abstract. Missing rows: zero. One pass over out.
__global__ void scatter_zero_kernel(const float4* __restrict__ x4,
                                    float4* __restrict__ out4,
                                    int N, int Cv) {
    const int stride = gridDim.x * blockDim.x;
    const int tid = blockIdx.x * blockDim.x + threadIdx.x;
    const int total = N * Cv;
    for (int i = tid; i < total; i += stride) {
        const int n = i / Cv;
        const int c = i - n * Cv;
        const int p = g_pos[n];
        out4[i] = (p >= 0) ? x4[(size_t)p * Cv + c]
                           : make_float4(0.f, 0.f, 0.f, 0.f);
    }
}

// Insert (t,s) into hash; returns true if first occurrence AND source present,
// and writes pooled source row to *ps_out. Always bumps cnt[t] on first win.
__device__ __forceinline__ bool try_insert(int t, int s, int N, int* ps_out) {
    if (t == s) return false;
    if (g_pos[t] >= 0) return false;            // only missing targets matter
    const uint64_t key = (uint64_t)t * (uint64_t)N + (uint64_t)s + 1ULL;
    unsigned h = (unsigned)mix64(key) & (TAB_SIZE - 1);
    while (true) {
        unsigned long long old = atomicCAS(&g_hash[h], 0ULL, key);
        if (old == 0ULL) {                       // won: unique (t,s)
            atomicAdd(&g_cnt[t], 1);             // no return use -> RED
            int ps = g_pos[s];
            if (ps >= 0) { *ps_out = ps; return true; }
            return false;
        }
        if (old == key) return false;            // duplicate
        h = (h + 1) & (TAB_SIZE - 1);
    }
}

// Warp-aggregated append of (t, ps) pairs to the worklist.
__device__ __forceinline__ void warp_append(bool want, int t, int ps) {
    const unsigned bal = __ballot_sync(0xffffffffu, want);
    if (bal == 0u) return;
    const int lane = threadIdx.x & 31;
    const int leader = __ffs(bal) - 1;
    int base = 0;
    if (lane == leader) base = atomicAdd(&g_wl_count, __popc(bal));
    base = __shfl_sync(0xffffffffu, base, leader);
    if (want) {
        const int off = __popc(bal & ((1u << lane) - 1u));
        g_wl[base + off] = make_int2(t, ps);
    }
}

// One thread per undirected edge; handles both directed pairs. NO early
// returns before the warp-collective appends.
__global__ void edge_kernel(const int* __restrict__ e0,
                            const int* __restrict__ e1,
                            int E, int N) {
    const int j = blockIdx.x * blockDim.x + threadIdx.x;
    const bool valid = (j < E);
    int a = 0, b = 0;
    if (valid) { a = e0[j]; b = e1[j]; }

    int ps0 = -1, ps1 = -1;
    bool ap0 = valid && try_insert(a, b, N, &ps0);   // direction (a<-b)
    bool ap1 = valid && try_insert(b, a, N, &ps1);   // direction (b<-a)

    warp_append(ap0, a, ps0);
    warp_append(ap1, b, ps1);
}

// 16 lanes per worklist item, float4 per lane, vector red into out.
__global__ void feat_kernel(const float4* __restrict__ xa4,
                            float4* __restrict__ out4, int Cv) {
    const int lane = threadIdx.x & 31;
    const int li   = lane & 15;            // lane within half-warp
    const int sub  = lane >> 4;            // which of the 2 items this warp does
    const int warp = (blockIdx.x * blockDim.x + threadIdx.x) >> 5;
    const int nwarps = (gridDim.x * blockDim.x) >> 5;
    const int n = g_wl_count;
    for (int i = warp * 2 + sub; i < n; i += nwarps * 2) {
        const int2 w = g_wl[i];
        const float4 v = xa4[(size_t)w.y * Cv + li];
        float4* dst = out4 + (size_t)w.x * Cv + li;
        asm volatile("red.global.add.v4.f32 [%0], {%1, %2, %3, %4};"
                     :: "l"(dst), "f"(v.x), "f"(v.y), "f"(v.z), "f"(v.w)
                     : "memory");
    }
}

// Divide missing rows by their unique-neighbor count.
__global__ void finalize_kernel(float4* __restrict__ out4, int N, int Cv) {
    const int stride = gridDim.x * blockDim.x;
    const int tid = blockIdx.x * blockDim.x + threadIdx.x;
    const int total = N * Cv;
    for (int i = tid; i < total; i += stride) {
        const int n = i / Cv;
        if (g_pos[n] < 0) {
            const int c = g_cnt[n];
            if (c > 0) {
                const float inv = 1.0f / (float)c;
                float4 v = out4[i];
                v.x *= inv; v.y *= inv; v.z *= inv; v.w *= inv;
                out4[i] = v;
            }
        }
    }
}

extern "C" void kernel_launch(void* const* d_in, const int* in_sizes, int n_in,
                              void* d_out, int out_size) {
    const float* xa   = (const float*)d_in[0];   // [P, C] f32
    const int*   perm = (const int*)d_in[1];     // [P]
    const int*   ei   = (const int*)d_in[2];     // [2, E]
    (void)n_in;

    const int P  = in_sizes[1];
    const int C  = in_sizes[0] / P;              // 64
    const int Cv = C / 4;                        // 16
    const int E  = in_sizes[2] / 2;
    const int N  = out_size / C;                 // 100000
    float* out = (float*)d_out;

    clear_kernel<<<1024, 256>>>(N);
    pos_kernel<<<(P + 255) / 256, 256>>>(perm, P);

    {
        int work = N * Cv;
        int blocks = (work + 255) / 256;
        if (blocks > 4096) blocks = 4096;
        scatter_zero_kernel<<<blocks, 256>>>((const float4*)xa, (float4*)out, N, Cv);
    }

    edge_kernel<<<(E + 255) / 256, 256>>>(ei, ei + E, E, N);

    feat_kernel<<<2048, 256>>>((const float4*)xa, (float4*)out, Cv);

    finalize_kernel<<<2048, 256>>>((float4*)out, N, Cv);
}

// round 3
// speedup vs baseline: 1.9479x; 1.0966x over previous
#include <cuda_runtime.h>
#include <stdint.h>

// ---------------------------------------------------------------------------
// AdaptiveUnpooling v3:
//   - ONE canonical hash insert per undirected edge (min,max) decides
//     uniqueness for both directions (symmetric directed pair set).
//   - skip edges with both endpoints present (they affect nothing).
//   - warp-aggregated worklist append (<=1 per edge by construction).
//   - row-based scatter + compacted missing list for finalize.
// ---------------------------------------------------------------------------

#define TAB_BITS 22
#define TAB_SIZE (1u << TAB_BITS)      // 4M slots * 8B = 32MB (L2-resident)
#define MAX_N    131072
#define WL_MAX   2600000

__device__ unsigned long long g_hash[TAB_SIZE];
__device__ int  g_cnt[MAX_N];
__device__ int  g_pos[MAX_N];
__device__ int  g_wl_count;
__device__ int2 g_wl[WL_MAX];
__device__ int  g_miss_count;
__device__ int  g_miss[MAX_N];

__device__ __forceinline__ uint64_t mix64(uint64_t x) {
    x ^= x >> 33; x *= 0xff51afd7ed558ccdULL;
    x ^= x >> 33; x *= 0xc4ceb9fe1a85ec53ULL;
    x ^= x >> 33;
    return x;
}

// Zero hash table + counters; pos = -1; list counters = 0.
__global__ void clear_kernel(int N) {
    const int stride = gridDim.x * blockDim.x;
    const int tid = blockIdx.x * blockDim.x + threadIdx.x;
    ulonglong2* h2 = reinterpret_cast<ulonglong2*>(g_hash);
    for (unsigned i = tid; i < TAB_SIZE / 2; i += stride)
        h2[i] = make_ulonglong2(0ULL, 0ULL);
    for (int i = tid; i < N; i += stride) { g_cnt[i] = 0; g_pos[i] = -1; }
    if (tid == 0) { g_wl_count = 0; g_miss_count = 0; }
}

// pos[perm[i]] = i
__global__ void pos_kernel(const int* __restrict__ perm, int P) {
    const int i = blockIdx.x * blockDim.x + threadIdx.x;
    if (i < P) g_pos[perm[i]] = i;
}

// Generic warp-aggregated append of a packed payload into a list.
__device__ __forceinline__ void warp_append_i2(bool want, int2 v,
                                               int* counter, int2* list) {
    const unsigned bal = __ballot_sync(0xffffffffu, want);
    if (bal == 0u) return;
    const int lane = threadIdx.x & 31;
    const int leader = __ffs(bal) - 1;
    int base = 0;
    if (lane == leader) base = atomicAdd(counter, __popc(bal));
    base = __shfl_sync(0xffffffffu, base, leader);
    if (want) list[base + __popc(bal & ((1u << lane) - 1u))] = v;
}

__device__ __forceinline__ void warp_append_i1(bool want, int v,
                                               int* counter, int* list) {
    const unsigned bal = __ballot_sync(0xffffffffu, want);
    if (bal == 0u) return;
    const int lane = threadIdx.x & 31;
    const int leader = __ffs(bal) - 1;
    int base = 0;
    if (lane == leader) base = atomicAdd(counter, __popc(bal));
    base = __shfl_sync(0xffffffffu, base, leader);
    if (want) list[base + __popc(bal & ((1u << lane) - 1u))] = v;
}

// Rows: present -> copy from x_abstract, missing -> zero + record in miss list.
// One pos load per row (Cv threads per row).
__global__ void scatter_zero_kernel(const float4* __restrict__ x4,
                                    float4* __restrict__ out4,
                                    int N, int Cv) {
    const int gtid = blockIdx.x * blockDim.x + threadIdx.x;
    const int row  = gtid / Cv;
    const int c    = gtid - row * Cv;
    const bool valid = (row < N);
    int p = 0;
    if (valid) {
        p = g_pos[row];
        out4[(size_t)row * Cv + c] = (p >= 0)
            ? x4[(size_t)p * Cv + c]
            : make_float4(0.f, 0.f, 0.f, 0.f);
    }
    warp_append_i1(valid && c == 0 && p < 0, row, &g_miss_count, g_miss);
}

// One thread per undirected edge. One canonical CAS decides both directions.
__global__ void edge_kernel(const int* __restrict__ e0,
                            const int* __restrict__ e1,
                            int E, int N) {
    const int j = blockIdx.x * blockDim.x + threadIdx.x;
    const bool valid = (j < E);
    int a = 0, b = 0;
    if (valid) { a = e0[j]; b = e1[j]; }

    int pa = 0, pb = 0;
    bool act = valid && (a != b);
    if (act) {
        pa = g_pos[a];
        pb = g_pos[b];
        act = (pa < 0) || (pb < 0);       // both present -> nothing to do
    }

    bool win = false;
    if (act) {
        const int lo = min(a, b), hi = max(a, b);
        const uint64_t key = (uint64_t)lo * (uint64_t)N + (uint64_t)hi + 1ULL;
        unsigned h = (unsigned)mix64(key) & (TAB_SIZE - 1);
        while (true) {
            unsigned long long old = atomicCAS(&g_hash[h], 0ULL, key);
            if (old == 0ULL) { win = true; break; }   // unique undirected edge
            if (old == key)  { break; }               // duplicate
            h = (h + 1) & (TAB_SIZE - 1);
        }
    }

    if (win) {
        if (pa < 0) atomicAdd(&g_cnt[a], 1);          // fire-and-forget RED
        if (pb < 0) atomicAdd(&g_cnt[b], 1);
    }

    // a feature contribution needs exactly one endpoint missing
    const bool app = win && ((pa < 0) != (pb < 0));
    const int  t   = (pa < 0) ? a : b;
    const int  ps  = (pa < 0) ? pb : pa;
    warp_append_i2(app, make_int2(t, ps), &g_wl_count, g_wl);
}

// 16 lanes per worklist item, float4 per lane, vector red into out.
__global__ void feat_kernel(const float4* __restrict__ xa4,
                            float4* __restrict__ out4, int Cv) {
    const int lane = threadIdx.x & 31;
    const int li   = lane & 15;
    const int sub  = lane >> 4;
    const int warp = (blockIdx.x * blockDim.x + threadIdx.x) >> 5;
    const int nwarps = (gridDim.x * blockDim.x) >> 5;
    const int n = g_wl_count;
    for (int i = warp * 2 + sub; i < n; i += nwarps * 2) {
        const int2 w = g_wl[i];
        const float4 v = xa4[(size_t)w.y * Cv + li];
        float4* dst = out4 + (size_t)w.x * Cv + li;
        asm volatile("red.global.add.v4.f32 [%0], {%1, %2, %3, %4};"
                     :: "l"(dst), "f"(v.x), "f"(v.y), "f"(v.z), "f"(v.w)
                     : "memory");
    }
}

// Divide missing rows (from the compacted list) by their neighbor count.
__global__ void finalize_kernel(float4* __restrict__ out4, int Cv) {
    const int gtid = blockIdx.x * blockDim.x + threadIdx.x;
    const int idx  = gtid / Cv;
    const int c    = gtid - idx * Cv;
    if (idx >= g_miss_count) return;
    const int n   = g_miss[idx];
    const int cnt = g_cnt[n];
    if (cnt > 0) {
        const float inv = 1.0f / (float)cnt;
        float4 v = out4[(size_t)n * Cv + c];
        v.x *= inv; v.y *= inv; v.z *= inv; v.w *= inv;
        out4[(size_t)n * Cv + c] = v;
    }
}

extern "C" void kernel_launch(void* const* d_in, const int* in_sizes, int n_in,
                              void* d_out, int out_size) {
    const float* xa   = (const float*)d_in[0];   // [P, C] f32
    const int*   perm = (const int*)d_in[1];     // [P]
    const int*   ei   = (const int*)d_in[2];     // [2, E]
    (void)n_in;

    const int P  = in_sizes[1];
    const int C  = in_sizes[0] / P;              // 64
    const int Cv = C / 4;                        // 16
    const int E  = in_sizes[2] / 2;
    const int N  = out_size / C;                 // 100000
    float* out = (float*)d_out;

    clear_kernel<<<1024, 256>>>(N);
    pos_kernel<<<(P + 255) / 256, 256>>>(perm, P);

    {
        const int work = N * Cv;
        scatter_zero_kernel<<<(work + 255) / 256, 256>>>(
            (const float4*)xa, (float4*)out, N, Cv);
    }

    edge_kernel<<<(E + 255) / 256, 256>>>(ei, ei + E, E, N);

    feat_kernel<<<2048, 256>>>((const float4*)xa, (float4*)out, Cv);

    {
        const int work = N * Cv;   // upper bound on missing rows * Cv
        finalize_kernel<<<(work + 255) / 256, 256>>>((float4*)out, Cv);
    }
}

// round 4
// speedup vs baseline: 2.3264x; 1.1943x over previous
#include <cuda_runtime.h>
#include <stdint.h>

// ---------------------------------------------------------------------------
// AdaptiveUnpooling v4: ILP-batched edge kernel (4 edges/thread, phased),
// single warp-scan worklist append, canonical undirected hash insert.
// ---------------------------------------------------------------------------

#define TAB_BITS 22
#define TAB_SIZE (1u << TAB_BITS)      // 4M slots * 8B = 32MB (L2-resident)
#define MAX_N    131072
#define WL_MAX   2600000
#define UB       4                     // edges per thread

__device__ unsigned long long g_hash[TAB_SIZE];
__device__ int  g_cnt[MAX_N];
__device__ int  g_pos[MAX_N];
__device__ int  g_wl_count;
__device__ int2 g_wl[WL_MAX];
__device__ int  g_miss_count;
__device__ int  g_miss[MAX_N];

__device__ __forceinline__ uint64_t mix64(uint64_t x) {
    x ^= x >> 33; x *= 0xff51afd7ed558ccdULL;
    x ^= x >> 33; x *= 0xc4ceb9fe1a85ec53ULL;
    x ^= x >> 33;
    return x;
}

__global__ void clear_kernel(int N) {
    const int stride = gridDim.x * blockDim.x;
    const int tid = blockIdx.x * blockDim.x + threadIdx.x;
    ulonglong2* h2 = reinterpret_cast<ulonglong2*>(g_hash);
    for (unsigned i = tid; i < TAB_SIZE / 2; i += stride)
        h2[i] = make_ulonglong2(0ULL, 0ULL);
    for (int i = tid; i < N; i += stride) { g_cnt[i] = 0; g_pos[i] = -1; }
    if (tid == 0) { g_wl_count = 0; g_miss_count = 0; }
}

__global__ void pos_kernel(const int* __restrict__ perm, int P) {
    const int i = blockIdx.x * blockDim.x + threadIdx.x;
    if (i < P) g_pos[perm[i]] = i;
}

__device__ __forceinline__ void warp_append_i1(bool want, int v,
                                               int* counter, int* list) {
    const unsigned bal = __ballot_sync(0xffffffffu, want);
    if (bal == 0u) return;
    const int lane = threadIdx.x & 31;
    const int leader = __ffs(bal) - 1;
    int base = 0;
    if (lane == leader) base = atomicAdd(counter, __popc(bal));
    base = __shfl_sync(0xffffffffu, base, leader);
    if (want) list[base + __popc(bal & ((1u << lane) - 1u))] = v;
}

// Rows: present -> copy from x_abstract, missing -> zero + record in miss list.
__global__ void scatter_zero_kernel(const float4* __restrict__ x4,
                                    float4* __restrict__ out4,
                                    int N, int Cv) {
    const int gtid = blockIdx.x * blockDim.x + threadIdx.x;
    const int row  = gtid / Cv;
    const int c    = gtid - row * Cv;
    const bool valid = (row < N);
    int p = 0;
    if (valid) {
        p = g_pos[row];
        out4[(size_t)row * Cv + c] = (p >= 0)
            ? x4[(size_t)p * Cv + c]
            : make_float4(0.f, 0.f, 0.f, 0.f);
    }
    warp_append_i1(valid && c == 0 && p < 0, row, &g_miss_count, g_miss);
}

// 4 edges per thread, phased for MLP. One warp-scan append per batch.
__global__ void edge_kernel(const int* __restrict__ e0,
                            const int* __restrict__ e1,
                            int E, int N) {
    const int tid = blockIdx.x * blockDim.x + threadIdx.x;
    const int TOT = gridDim.x * blockDim.x;
    const int lane = threadIdx.x & 31;

    int a[UB], b[UB], pa[UB], pb[UB];
    bool act[UB];

    // Phase 1: coalesced edge loads
    #pragma unroll
    for (int k = 0; k < UB; k++) {
        const int j = tid + k * TOT;
        const bool v = (j < E);
        act[k] = v;
        a[k] = v ? e0[j] : 0;
        b[k] = v ? e1[j] : 1;            // a!=b for inactive lanes
    }

    // Phase 2: 8 independent pos loads
    #pragma unroll
    for (int k = 0; k < UB; k++) {
        act[k] = act[k] && (a[k] != b[k]);
        pa[k] = act[k] ? g_pos[a[k]] : 0;
        pb[k] = act[k] ? g_pos[b[k]] : 0;
        act[k] = act[k] && ((pa[k] < 0) || (pb[k] < 0));
    }

    // Phase 3: canonical keys + batched first-probe CAS
    uint64_t key[UB];
    unsigned h[UB];
    unsigned long long old[UB];
    #pragma unroll
    for (int k = 0; k < UB; k++) {
        const int lo = min(a[k], b[k]), hi = max(a[k], b[k]);
        key[k] = (uint64_t)lo * (uint64_t)N + (uint64_t)hi + 1ULL;
        h[k] = (unsigned)mix64(key[k]) & (TAB_SIZE - 1);
    }
    #pragma unroll
    for (int k = 0; k < UB; k++)
        old[k] = act[k] ? atomicCAS(&g_hash[h[k]], 0ULL, key[k]) : 1ULL;

    // Phase 4: resolve rare collisions, decide wins
    bool win[UB];
    #pragma unroll
    for (int k = 0; k < UB; k++) {
        win[k] = false;
        if (act[k]) {
            unsigned long long o = old[k];
            unsigned hh = h[k];
            while (o != 0ULL && o != key[k]) {
                hh = (hh + 1) & (TAB_SIZE - 1);
                o = atomicCAS(&g_hash[hh], 0ULL, key[k]);
            }
            win[k] = (o == 0ULL);
        }
    }

    // Phase 5: fire-and-forget count bumps
    #pragma unroll
    for (int k = 0; k < UB; k++) {
        if (win[k]) {
            if (pa[k] < 0) atomicAdd(&g_cnt[a[k]], 1);
            if (pb[k] < 0) atomicAdd(&g_cnt[b[k]], 1);
        }
    }

    // Phase 6: single warp-scan append of all items from this batch
    bool app[UB];
    int m = 0;
    #pragma unroll
    for (int k = 0; k < UB; k++) {
        app[k] = win[k] && ((pa[k] < 0) != (pb[k] < 0));
        m += app[k] ? 1 : 0;
    }
    int pref = m;
    #pragma unroll
    for (int d = 1; d < 32; d <<= 1) {
        int v = __shfl_up_sync(0xffffffffu, pref, d);
        if (lane >= d) pref += v;
    }
    const int total = __shfl_sync(0xffffffffu, pref, 31);
    int base = 0;
    if (total > 0) {
        if (lane == 0) base = atomicAdd(&g_wl_count, total);
        base = __shfl_sync(0xffffffffu, base, 0);
        int off = base + (pref - m);
        #pragma unroll
        for (int k = 0; k < UB; k++) {
            if (app[k]) {
                const int t  = (pa[k] < 0) ? a[k] : b[k];
                const int ps = (pa[k] < 0) ? pb[k] : pa[k];
                g_wl[off++] = make_int2(t, ps);
            }
        }
    }
}

// 16 lanes per worklist item, float4 per lane, vector red into out.
__global__ void feat_kernel(const float4* __restrict__ xa4,
                            float4* __restrict__ out4, int Cv) {
    const int lane = threadIdx.x & 31;
    const int li   = lane & 15;
    const int sub  = lane >> 4;
    const int warp = (blockIdx.x * blockDim.x + threadIdx.x) >> 5;
    const int nwarps = (gridDim.x * blockDim.x) >> 5;
    const int n = g_wl_count;
    for (int i = warp * 2 + sub; i < n; i += nwarps * 2) {
        const int2 w = g_wl[i];
        const float4 v = xa4[(size_t)w.y * Cv + li];
        float4* dst = out4 + (size_t)w.x * Cv + li;
        asm volatile("red.global.add.v4.f32 [%0], {%1, %2, %3, %4};"
                     :: "l"(dst), "f"(v.x), "f"(v.y), "f"(v.z), "f"(v.w)
                     : "memory");
    }
}

// Divide missing rows (compacted list) by their neighbor count.
__global__ void finalize_kernel(float4* __restrict__ out4, int Cv) {
    const int gtid = blockIdx.x * blockDim.x + threadIdx.x;
    const int idx  = gtid / Cv;
    const int c    = gtid - idx * Cv;
    if (idx >= g_miss_count) return;
    const int n   = g_miss[idx];
    const int cnt = g_cnt[n];
    if (cnt > 0) {
        const float inv = 1.0f / (float)cnt;
        float4 v = out4[(size_t)n * Cv + c];
        v.x *= inv; v.y *= inv; v.z *= inv; v.w *= inv;
        out4[(size_t)n * Cv + c] = v;
    }
}

extern "C" void kernel_launch(void* const* d_in, const int* in_sizes, int n_in,
                              void* d_out, int out_size) {
    const float* xa   = (const float*)d_in[0];   // [P, C] f32
    const int*   perm = (const int*)d_in[1];     // [P]
    const int*   ei   = (const int*)d_in[2];     // [2, E]
    (void)n_in;

    const int P  = in_sizes[1];
    const int C  = in_sizes[0] / P;              // 64
    const int Cv = C / 4;                        // 16
    const int E  = in_sizes[2] / 2;
    const int N  = out_size / C;                 // 100000
    float* out = (float*)d_out;

    clear_kernel<<<1024, 256>>>(N);
    pos_kernel<<<(P + 255) / 256, 256>>>(perm, P);

    {
        const int work = N * Cv;
        scatter_zero_kernel<<<(work + 255) / 256, 256>>>(
            (const float4*)xa, (float4*)out, N, Cv);
    }

    {
        const int threads_needed = (E + UB - 1) / UB;
        const int blocks = (threads_needed + 255) / 256;
        edge_kernel<<<blocks, 256>>>(ei, ei + E, E, N);
    }

    feat_kernel<<<2048, 256>>>((const float4*)xa, (float4*)out, Cv);

    {
        const int work = N * Cv;
        finalize_kernel<<<(work + 255) / 256, 256>>>((float4*)out, Cv);
    }
}

// round 5
// speedup vs baseline: 2.5020x; 1.0754x over previous
#include <cuda_runtime.h>
#include <stdint.h>

// ---------------------------------------------------------------------------
// AdaptiveUnpooling v5:
//   - edge dedup: canonical undirected key, 8-edge ILP batches, batched CAS.
//   - per-target linked lists built with atomicExch during dedup.
//   - gather kernel: 16 lanes/node walk the chain, register-accumulate,
//     single non-atomic write of mean (or zeros). No feat atomics, no
//     finalize pass, no missing-row pre-zeroing.
// ---------------------------------------------------------------------------

#define TAB_BITS 22
#define TAB_SIZE (1u << TAB_BITS)      // 4M slots * 8B = 32MB (L2-resident)
#define MAX_N    131072
#define WL_MAX   2600000
#define UB       8                     // edges per thread

__device__ unsigned long long g_hash[TAB_SIZE];
__device__ int  g_cnt[MAX_N];          // unique-neighbor count (missing nodes)
__device__ int  g_pos[MAX_N];          // pooled row or -1
__device__ int  g_head[MAX_N];         // head of per-target item chain, -1
__device__ int  g_wl_count;
__device__ int2 g_items[WL_MAX];       // {pooled src row, next item idx}

__device__ __forceinline__ uint64_t mix64(uint64_t x) {
    x ^= x >> 33; x *= 0xff51afd7ed558ccdULL;
    x ^= x >> 33; x *= 0xc4ceb9fe1a85ec53ULL;
    x ^= x >> 33;
    return x;
}

__global__ void clear_kernel(int N) {
    const int stride = gridDim.x * blockDim.x;
    const int tid = blockIdx.x * blockDim.x + threadIdx.x;
    ulonglong2* h2 = reinterpret_cast<ulonglong2*>(g_hash);
    for (unsigned i = tid; i < TAB_SIZE / 2; i += stride)
        h2[i] = make_ulonglong2(0ULL, 0ULL);
    for (int i = tid; i < N; i += stride) {
        g_cnt[i] = 0; g_pos[i] = -1; g_head[i] = -1;
    }
    if (tid == 0) g_wl_count = 0;
}

__global__ void pos_kernel(const int* __restrict__ perm, int P) {
    const int i = blockIdx.x * blockDim.x + threadIdx.x;
    if (i < P) g_pos[perm[i]] = i;
}

// Copy present rows only: out[perm[r]] = xa[r].
__global__ void scatter_kernel(const float4* __restrict__ x4,
                               const int* __restrict__ perm,
                               float4* __restrict__ out4,
                               int P, int Cv) {
    const int gtid = blockIdx.x * blockDim.x + threadIdx.x;
    const int r = gtid / Cv;
    const int c = gtid - r * Cv;
    if (r < P)
        out4[(size_t)perm[r] * Cv + c] = x4[(size_t)r * Cv + c];
}

// 8 edges per thread, phased for MLP. Warp-scan append + linked-list insert.
__global__ void edge_kernel(const int* __restrict__ e0,
                            const int* __restrict__ e1,
                            int E, int N) {
    const int tid = blockIdx.x * blockDim.x + threadIdx.x;
    const int TOT = gridDim.x * blockDim.x;
    const int lane = threadIdx.x & 31;

    int a[UB], b[UB], pa[UB], pb[UB];
    bool act[UB];

    // Phase 1: coalesced edge loads
    #pragma unroll
    for (int k = 0; k < UB; k++) {
        const int j = tid + k * TOT;
        const bool v = (j < E);
        act[k] = v;
        a[k] = v ? e0[j] : 0;
        b[k] = v ? e1[j] : 1;
    }

    // Phase 2: independent pos loads
    #pragma unroll
    for (int k = 0; k < UB; k++) {
        act[k] = act[k] && (a[k] != b[k]);
        pa[k] = act[k] ? g_pos[a[k]] : 0;
        pb[k] = act[k] ? g_pos[b[k]] : 0;
        act[k] = act[k] && ((pa[k] < 0) || (pb[k] < 0));
    }

    // Phase 3: canonical keys + batched first-probe CAS
    unsigned h[UB];
    unsigned long long old[UB];
    #pragma unroll
    for (int k = 0; k < UB; k++) {
        const int lo = min(a[k], b[k]), hi = max(a[k], b[k]);
        const uint64_t key = (uint64_t)lo * (uint64_t)N + (uint64_t)hi + 1ULL;
        h[k] = (unsigned)mix64(key) & (TAB_SIZE - 1);
        old[k] = act[k] ? atomicCAS(&g_hash[h[k]], 0ULL, key) : 1ULL;
    }

    // Phase 4: resolve rare collisions
    bool win[UB];
    #pragma unroll
    for (int k = 0; k < UB; k++) {
        win[k] = false;
        if (act[k]) {
            const int lo = min(a[k], b[k]), hi = max(a[k], b[k]);
            const uint64_t key = (uint64_t)lo * (uint64_t)N + (uint64_t)hi + 1ULL;
            unsigned long long o = old[k];
            unsigned hh = h[k];
            while (o != 0ULL && o != key) {
                hh = (hh + 1) & (TAB_SIZE - 1);
                o = atomicCAS(&g_hash[hh], 0ULL, key);
            }
            win[k] = (o == 0ULL);
        }
    }

    // Phase 5: fire-and-forget count bumps
    #pragma unroll
    for (int k = 0; k < UB; k++) {
        if (win[k]) {
            if (pa[k] < 0) atomicAdd(&g_cnt[a[k]], 1);
            if (pb[k] < 0) atomicAdd(&g_cnt[b[k]], 1);
        }
    }

    // Phase 6: warp-scan bulk append + per-item linked-list insert
    bool app[UB];
    int m = 0;
    #pragma unroll
    for (int k = 0; k < UB; k++) {
        app[k] = win[k] && ((pa[k] < 0) != (pb[k] < 0));
        m += app[k] ? 1 : 0;
    }
    int pref = m;
    #pragma unroll
    for (int d = 1; d < 32; d <<= 1) {
        int v = __shfl_up_sync(0xffffffffu, pref, d);
        if (lane >= d) pref += v;
    }
    const int total = __shfl_sync(0xffffffffu, pref, 31);
    if (total > 0) {
        int base = 0;
        if (lane == 0) base = atomicAdd(&g_wl_count, total);
        base = __shfl_sync(0xffffffffu, base, 0);
        int idx = base + (pref - m);
        #pragma unroll
        for (int k = 0; k < UB; k++) {
            if (app[k]) {
                const int t  = (pa[k] < 0) ? a[k] : b[k];
                const int ps = (pa[k] < 0) ? pb[k] : pa[k];
                const int prev = atomicExch(&g_head[t], idx);
                g_items[idx] = make_int2(ps, prev);
                idx++;
            }
        }
    }
}

// 16 lanes per node: present -> skip; missing -> walk chain, accumulate row
// in registers, write mean (or zeros) once, non-atomically.
__global__ void gather_kernel(const float4* __restrict__ xa4,
                              float4* __restrict__ out4,
                              int N, int Cv) {
    const int lane = threadIdx.x & 31;
    const int li   = lane & 15;
    const int sub  = lane >> 4;
    const int warp = (blockIdx.x * blockDim.x + threadIdx.x) >> 5;
    const int t = warp * 2 + sub;
    if (t >= N) return;
    if (g_pos[t] >= 0) return;                  // present: scatter handled it

    float4 acc = make_float4(0.f, 0.f, 0.f, 0.f);
    int cur = g_head[t];                        // uniform within 16-lane group
    while (cur >= 0) {
        const int2 it = g_items[cur];           // L1-broadcast across lanes
        const float4 v = xa4[(size_t)it.x * Cv + li];
        acc.x += v.x; acc.y += v.y; acc.z += v.z; acc.w += v.w;
        cur = it.y;
    }
    const int cnt = g_cnt[t];
    const float inv = (cnt > 0) ? 1.0f / (float)cnt : 0.0f;
    acc.x *= inv; acc.y *= inv; acc.z *= inv; acc.w *= inv;
    out4[(size_t)t * Cv + li] = acc;
}

extern "C" void kernel_launch(void* const* d_in, const int* in_sizes, int n_in,
                              void* d_out, int out_size) {
    const float* xa   = (const float*)d_in[0];   // [P, C] f32
    const int*   perm = (const int*)d_in[1];     // [P]
    const int*   ei   = (const int*)d_in[2];     // [2, E]
    (void)n_in;

    const int P  = in_sizes[1];
    const int C  = in_sizes[0] / P;              // 64
    const int Cv = C / 4;                        // 16
    const int E  = in_sizes[2] / 2;
    const int N  = out_size / C;                 // 100000
    float* out = (float*)d_out;

    clear_kernel<<<1024, 256>>>(N);
    pos_kernel<<<(P + 255) / 256, 256>>>(perm, P);

    {
        const int work = P * Cv;
        scatter_kernel<<<(work + 255) / 256, 256>>>(
            (const float4*)xa, perm, (float4*)out, P, Cv);
    }

    {
        const int threads_needed = (E + UB - 1) / UB;
        edge_kernel<<<(threads_needed + 255) / 256, 256>>>(ei, ei + E, E, N);
    }

    {
        const int work = N * 16;                 // 16 lanes per node
        gather_kernel<<<(work + 255) / 256, 256>>>(
            (const float4*)xa, (float4*)out, N, Cv);
    }
}

// round 6
// speedup vs baseline: 2.7404x; 1.0953x over previous
#include <cuda_runtime.h>
#include <stdint.h>

// ---------------------------------------------------------------------------
// AdaptiveUnpooling v6:
//   - edge dedup: canonical undirected key, UB=4 ILP batches, batched CAS,
//     __launch_bounds__(256,5) + exact-wave grid-stride (no tail wave).
//   - per-target linked lists built with atomicExch during dedup.
//   - gather kernel: 16 lanes/node walk chain, register-accumulate, single
//     non-atomic write of mean.
// ---------------------------------------------------------------------------

#define TAB_BITS 22
#define TAB_SIZE (1u << TAB_BITS)      // 4M slots * 8B = 32MB (L2-resident)
#define MAX_N    131072
#define WL_MAX   2600000
#define UB       4                     // edges per batch per thread
#define EDGE_BLOCKS  740               // 148 SMs * 5 blocks/SM
#define EDGE_THREADS 256

__device__ unsigned long long g_hash[TAB_SIZE];
__device__ int  g_cnt[MAX_N];          // unique-neighbor count
__device__ int  g_pos[MAX_N];          // pooled row or -1
__device__ int  g_head[MAX_N];         // head of per-target item chain, -1
__device__ int  g_wl_count;
__device__ int2 g_items[WL_MAX];       // {pooled src row, next item idx}

__device__ __forceinline__ uint64_t mix64(uint64_t x) {
    x ^= x >> 33; x *= 0xff51afd7ed558ccdULL;
    x ^= x >> 33; x *= 0xc4ceb9fe1a85ec53ULL;
    x ^= x >> 33;
    return x;
}

__global__ void clear_kernel(int N) {
    const int stride = gridDim.x * blockDim.x;
    const int tid = blockIdx.x * blockDim.x + threadIdx.x;
    ulonglong2* h2 = reinterpret_cast<ulonglong2*>(g_hash);
    for (unsigned i = tid; i < TAB_SIZE / 2; i += stride)
        h2[i] = make_ulonglong2(0ULL, 0ULL);
    for (int i = tid; i < N; i += stride) {
        g_cnt[i] = 0; g_pos[i] = -1; g_head[i] = -1;
    }
    if (tid == 0) g_wl_count = 0;
}

__global__ void pos_kernel(const int* __restrict__ perm, int P) {
    const int i = blockIdx.x * blockDim.x + threadIdx.x;
    if (i < P) g_pos[perm[i]] = i;
}

// Copy present rows only: out[perm[r]] = xa[r].
__global__ void scatter_kernel(const float4* __restrict__ x4,
                               const int* __restrict__ perm,
                               float4* __restrict__ out4,
                               int P, int Cv) {
    const int gtid = blockIdx.x * blockDim.x + threadIdx.x;
    const int r = gtid / Cv;
    const int c = gtid - r * Cv;
    if (r < P)
        out4[(size_t)perm[r] * Cv + c] = x4[(size_t)r * Cv + c];
}

// UB edges per batch per thread, phased for MLP; exact-wave grid-stride.
__global__ void __launch_bounds__(EDGE_THREADS, 5)
edge_kernel(const int* __restrict__ e0,
            const int* __restrict__ e1,
            int E, int N) {
    const int tid = blockIdx.x * blockDim.x + threadIdx.x;
    const int TOT = gridDim.x * blockDim.x;
    const int lane = threadIdx.x & 31;
    const int step = TOT * UB;

    for (int base = tid; base < E + (step - 1); base += step) {
        // NOTE: every thread in a warp runs the same number of iterations
        // (uniform base progression), so warp-collectives below are safe.
        int a[UB], b[UB], pa[UB], pb[UB];
        bool act[UB];

        // Phase 1: coalesced edge loads
        #pragma unroll
        for (int k = 0; k < UB; k++) {
            const int j = base + k * TOT;
            const bool v = (j < E);
            act[k] = v;
            a[k] = v ? e0[j] : 0;
            b[k] = v ? e1[j] : 1;
        }

        // Phase 2: independent pos loads
        #pragma unroll
        for (int k = 0; k < UB; k++) {
            act[k] = act[k] && (a[k] != b[k]);
            pa[k] = act[k] ? g_pos[a[k]] : 0;
            pb[k] = act[k] ? g_pos[b[k]] : 0;
            act[k] = act[k] && ((pa[k] < 0) || (pb[k] < 0));
        }

        // Phase 3: canonical keys + batched first-probe CAS
        unsigned h[UB];
        unsigned long long old[UB];
        #pragma unroll
        for (int k = 0; k < UB; k++) {
            const int lo = min(a[k], b[k]), hi = max(a[k], b[k]);
            const uint64_t key = (uint64_t)lo * (uint64_t)N + (uint64_t)hi + 1ULL;
            h[k] = (unsigned)mix64(key) & (TAB_SIZE - 1);
            old[k] = act[k] ? atomicCAS(&g_hash[h[k]], 0ULL, key) : 1ULL;
        }

        // Phase 4: resolve rare collisions
        bool win[UB];
        #pragma unroll
        for (int k = 0; k < UB; k++) {
            win[k] = false;
            if (act[k]) {
                const int lo = min(a[k], b[k]), hi = max(a[k], b[k]);
                const uint64_t key = (uint64_t)lo * (uint64_t)N + (uint64_t)hi + 1ULL;
                unsigned long long o = old[k];
                unsigned hh = h[k];
                while (o != 0ULL && o != key) {
                    hh = (hh + 1) & (TAB_SIZE - 1);
                    o = atomicCAS(&g_hash[hh], 0ULL, key);
                }
                win[k] = (o == 0ULL);
            }
        }

        // Phase 5: fire-and-forget count bumps
        #pragma unroll
        for (int k = 0; k < UB; k++) {
            if (win[k]) {
                if (pa[k] < 0) atomicAdd(&g_cnt[a[k]], 1);
                if (pb[k] < 0) atomicAdd(&g_cnt[b[k]], 1);
            }
        }

        // Phase 6: warp-scan bulk append + per-item linked-list insert
        bool app[UB];
        int m = 0;
        #pragma unroll
        for (int k = 0; k < UB; k++) {
            app[k] = win[k] && ((pa[k] < 0) != (pb[k] < 0));
            m += app[k] ? 1 : 0;
        }
        int pref = m;
        #pragma unroll
        for (int d = 1; d < 32; d <<= 1) {
            int v = __shfl_up_sync(0xffffffffu, pref, d);
            if (lane >= d) pref += v;
        }
        const int total = __shfl_sync(0xffffffffu, pref, 31);
        if (total > 0) {
            int wbase = 0;
            if (lane == 0) wbase = atomicAdd(&g_wl_count, total);
            wbase = __shfl_sync(0xffffffffu, wbase, 0);
            int idx = wbase + (pref - m);
            #pragma unroll
            for (int k = 0; k < UB; k++) {
                if (app[k]) {
                    const int t  = (pa[k] < 0) ? a[k] : b[k];
                    const int ps = (pa[k] < 0) ? pb[k] : pa[k];
                    const int prev = atomicExch(&g_head[t], idx);
                    g_items[idx] = make_int2(ps, prev);
                    idx++;
                }
            }
        }
    }
}

// 16 lanes per node: present -> skip; missing -> walk chain, accumulate row
// in registers, write mean (or zeros) once, non-atomically.
__global__ void gather_kernel(const float4* __restrict__ xa4,
                              float4* __restrict__ out4,
                              int N, int Cv) {
    const int lane = threadIdx.x & 31;
    const int li   = lane & 15;
    const int sub  = lane >> 4;
    const int warp = (blockIdx.x * blockDim.x + threadIdx.x) >> 5;
    const int t = warp * 2 + sub;
    if (t >= N) return;
    if (g_pos[t] >= 0) return;

    float4 acc = make_float4(0.f, 0.f, 0.f, 0.f);
    int cur = g_head[t];
    while (cur >= 0) {
        const int2 it = g_items[cur];
        const float4 v = xa4[(size_t)it.x * Cv + li];
        acc.x += v.x; acc.y += v.y; acc.z += v.z; acc.w += v.w;
        cur = it.y;
    }
    const int cnt = g_cnt[t];
    const float inv = (cnt > 0) ? 1.0f / (float)cnt : 0.0f;
    acc.x *= inv; acc.y *= inv; acc.z *= inv; acc.w *= inv;
    out4[(size_t)t * Cv + li] = acc;
}

extern "C" void kernel_launch(void* const* d_in, const int* in_sizes, int n_in,
                              void* d_out, int out_size) {
    const float* xa   = (const float*)d_in[0];   // [P, C] f32
    const int*   perm = (const int*)d_in[1];     // [P]
    const int*   ei   = (const int*)d_in[2];     // [2, E]
    (void)n_in;

    const int P  = in_sizes[1];
    const int C  = in_sizes[0] / P;              // 64
    const int Cv = C / 4;                        // 16
    const int E  = in_sizes[2] / 2;
    const int N  = out_size / C;                 // 100000
    float* out = (float*)d_out;

    clear_kernel<<<1024, 256>>>(N);
    pos_kernel<<<(P + 255) / 256, 256>>>(perm, P);

    {
        const int work = P * Cv;
        scatter_kernel<<<(work + 255) / 256, 256>>>(
            (const float4*)xa, perm, (float4*)out, P, Cv);
    }

    edge_kernel<<<EDGE_BLOCKS, EDGE_THREADS>>>(ei, ei + E, E, N);

    {
        const int work = N * 16;                 // 16 lanes per node
        gather_kernel<<<(work + 255) / 256, 256>>>(
            (const float4*)xa, (float4*)out, N, Cv);
    }
}